// round 9
// baseline (speedup 1.0000x reference)
#include <cuda_runtime.h>
#include <cuda_fp16.h>
#include <cstdint>

// ---------------------------------------------------------------------------
// Problem constants
// ---------------------------------------------------------------------------
#define M_DIM 4096      // out features
#define K_DIM 4096      // in features
#define N_DIM 8192      // cols of x / out
#define BM 128          // CTA tile M
#define BN 256          // CTA tile N
#define BK 64           // K per stage
#define KITERS (K_DIM / BK)   // 64 k-iters per tile
#define NTILES ((M_DIM / BM) * (N_DIM / BN))   // 32 x 32 = 1024
#define STAGES 4
#define THREADS 256     // 8 warps, 2(m) x 4(n), warp tile 64x64

// smem rows: 64 halves = 128B data + 16B pad = 144B (conflict-free ldmatrix)
#define ROW_B 144
#define A_STAGE_B (BM * ROW_B)            // 18432
#define B_STAGE_B (BN * ROW_B)            // 36864
#define STAGE_B (A_STAGE_B + B_STAGE_B)   // 55296
#define SMEM_TOTAL (STAGES * STAGE_B)     // 221184

// ---------------------------------------------------------------------------
// Device scratch. Packed k-major 64-wide panels:
//   elem(m, k) -> g_Wh[ ((k>>6)*M_DIM + m)*64 + (k&63) ]
//   elem(n, k) -> g_Xh[ ((k>>6)*N_DIM + n)*64 + (k&63) ]
// ---------------------------------------------------------------------------
__device__ unsigned short g_Wh[(size_t)M_DIM * K_DIM];   // 32 MB fp16
__device__ unsigned short g_Xh[(size_t)N_DIM * K_DIM];   // 64 MB fp16

// ---------------------------------------------------------------------------
// PTX helpers (sm_80-base ISA only)
// ---------------------------------------------------------------------------
__device__ __forceinline__ uint32_t smem_u32(const void* p) {
    uint32_t a;
    asm("{ .reg .u64 t; cvta.to.shared.u64 t, %1; cvt.u32.u64 %0, t; }" : "=r"(a) : "l"(p));
    return a;
}

__device__ __forceinline__ void cp16(uint32_t dst, const void* src) {
    asm volatile("cp.async.cg.shared.global [%0], [%1], 16;" :: "r"(dst), "l"(src));
}

#define CP_COMMIT() asm volatile("cp.async.commit_group;" ::: "memory")
#define CP_WAIT2()  asm volatile("cp.async.wait_group 2;" ::: "memory")

__device__ __forceinline__ void ldsm4(uint32_t r[4], uint32_t addr) {
    asm volatile("ldmatrix.sync.aligned.m8n8.x4.shared.b16 {%0,%1,%2,%3}, [%4];"
        : "=r"(r[0]), "=r"(r[1]), "=r"(r[2]), "=r"(r[3]) : "r"(addr));
}

__device__ __forceinline__ void mma16816(float d[4], const uint32_t a[4],
                                         uint32_t b0, uint32_t b1) {
    asm volatile(
        "mma.sync.aligned.m16n8k16.row.col.f32.f16.f16.f32 "
        "{%0,%1,%2,%3}, {%4,%5,%6,%7}, {%8,%9}, {%0,%1,%2,%3};"
        : "+f"(d[0]), "+f"(d[1]), "+f"(d[2]), "+f"(d[3])
        : "r"(a[0]), "r"(a[1]), "r"(a[2]), "r"(a[3]), "r"(b0), "r"(b1));
}

// ---------------------------------------------------------------------------
// Preprocessing: fused [packX | clearW] kernel, then scatter.
// grid = (64, 136): y < 128 -> packX 64x64 tile; y >= 128 -> clear W slice.
// ---------------------------------------------------------------------------
__global__ void prep_kernel(const float* __restrict__ x) {
    if (blockIdx.y < 128) {
        // ---- packX: transpose x[K,N] -> packed xT fp16 panels ----
        __shared__ float sh[64][65];
        const int k0 = blockIdx.x * 64;
        const int n0 = blockIdx.y * 64;
        const int t = threadIdx.x;    // 256 threads

        const float4* xv = reinterpret_cast<const float4*>(x + (size_t)k0 * N_DIM + n0);
#pragma unroll
        for (int i = 0; i < 4; ++i) {
            int idx = i * 256 + t;
            int kk = idx >> 4, c4 = idx & 15;
            float4 v = xv[(size_t)kk * (N_DIM / 4) + c4];
            sh[kk][c4 * 4 + 0] = v.x;
            sh[kk][c4 * 4 + 1] = v.y;
            sh[kk][c4 * 4 + 2] = v.z;
            sh[kk][c4 * 4 + 3] = v.w;
        }
        __syncthreads();
#pragma unroll
        for (int j = 0; j < 2; ++j) {  // 512 uint4 stores (64 n-rows x 8 octets)
            int idx = j * 256 + t;
            int nl = idx >> 3, oct = idx & 7;
            uint4 v;
            uint32_t* vp = &v.x;
#pragma unroll
            for (int q = 0; q < 4; ++q) {
                __half2 h2 = __floats2half2_rn(sh[oct * 8 + 2 * q][nl],
                                               sh[oct * 8 + 2 * q + 1][nl]);
                vp[q] = *reinterpret_cast<uint32_t*>(&h2);
            }
            size_t dst = ((size_t)blockIdx.x * N_DIM + n0 + nl) * 64 + oct * 8;
            *reinterpret_cast<uint4*>(&g_Xh[dst]) = v;
        }
    } else {
        // ---- clearW: 512 slices x 64KB ----
        int slice = blockIdx.x * 8 + (blockIdx.y - 128);   // 0..511
        uint4* p4 = reinterpret_cast<uint4*>(g_Wh) + (size_t)slice * 4096;
        uint4 z = make_uint4(0, 0, 0, 0);
#pragma unroll
        for (int i = 0; i < 16; ++i)
            p4[threadIdx.x + i * 256] = z;
    }
}

// Scatter COO directly into the packed fp16 panel layout with half atomics.
__global__ void scatter_kernel(const int* __restrict__ rows, const int* __restrict__ cols,
                               const float* __restrict__ vals, int nnz) {
    int i = blockIdx.x * blockDim.x + threadIdx.x;
    if (i < nnz) {
        int m = rows[i], k = cols[i];
        size_t idx = ((size_t)(k >> 6) * M_DIM + m) * 64 + (k & 63);
        atomicAdd(reinterpret_cast<__half*>(g_Wh) + idx, __float2half_rn(vals[i]));
    }
}

// ---------------------------------------------------------------------------
// Persistent GEMM: out = W(fp16) * x(fp16), fp32 accumulate. K = 4096.
// CTA 128x256x64, 8 warps (2m x 4n), warp 64x64, 4-stage cp.async.
// grid = #SMs; each CTA walks tiles t = blockIdx.x + p*gridDim.x through ONE
// continuous flat pipeline (loads run 3 stages ahead across tile boundaries),
// so the prologue is paid once and epilogues overlap the running pipeline.
// ---------------------------------------------------------------------------
__global__ void __launch_bounds__(THREADS, 1) gemm_kernel(float* __restrict__ out) {
    extern __shared__ __align__(128) char smem[];
    const uint32_t sb = smem_u32(smem);
    const int tid = threadIdx.x;
    const int lane = tid & 31;
    const int wid = tid >> 5;
    const int wm = (wid & 1) * 64;    // warp m offset
    const int wn = (wid >> 1) * 64;   // warp n offset

    float acc[4][8][4];
#pragma unroll
    for (int i = 0; i < 4; ++i)
#pragma unroll
        for (int j = 0; j < 8; ++j)
#pragma unroll
            for (int r = 0; r < 4; ++r) acc[i][j][r] = 0.f;

    const uint32_t a_lane_off =
        (uint32_t)((wm + (lane & 15)) * ROW_B + (lane >> 4) * 16);
    const uint32_t b_lane_off =
        (uint32_t)((wn + (lane & 7) + ((lane >> 4) & 1) * 8) * ROW_B +
                   ((lane >> 3) & 1) * 16);

    // load stage: coords given explicitly (tile m0/n0 + k-tile)
    auto load_stage = [&](int kt, int m0, int n0, int s) {
        const char* asrc = (const char*)g_Wh + ((size_t)kt * M_DIM + m0) * 128;
        const char* bsrc = (const char*)g_Xh + ((size_t)kt * N_DIM + n0) * 128;
        uint32_t As = sb + s * STAGE_B;
        uint32_t Bs = As + A_STAGE_B;
#pragma unroll
        for (int j = 0; j < 4; ++j) {   // A: 1024 x 16B chunks
            int c = tid + j * THREADS;
            cp16(As + (uint32_t)((c >> 3) * ROW_B + (c & 7) * 16), asrc + (size_t)c * 16);
        }
#pragma unroll
        for (int j = 0; j < 8; ++j) {   // B: 2048 x 16B chunks
            int c = tid + j * THREADS;
            cp16(Bs + (uint32_t)((c >> 3) * ROW_B + (c & 7) * 16), bsrc + (size_t)c * 16);
        }
    };

    auto ldsm_step = [&](int s, int ks, uint32_t a[4][4], uint32_t b[4][4]) {
        const uint32_t As = sb + s * STAGE_B + a_lane_off + ks * 32;
        const uint32_t Bs = sb + s * STAGE_B + A_STAGE_B + b_lane_off + ks * 32;
#pragma unroll
        for (int mi = 0; mi < 4; ++mi) ldsm4(a[mi], As + mi * (16 * ROW_B));
#pragma unroll
        for (int nj = 0; nj < 4; ++nj) ldsm4(b[nj], Bs + nj * (16 * ROW_B));
    };

    auto mma_step = [&](uint32_t a[4][4], uint32_t b[4][4]) {
#pragma unroll
        for (int mi = 0; mi < 4; ++mi)
#pragma unroll
            for (int nj = 0; nj < 4; ++nj) {
                mma16816(acc[mi][2 * nj], a[mi], b[nj][0], b[nj][1]);
                mma16816(acc[mi][2 * nj + 1], a[mi], b[nj][2], b[nj][3]);
            }
    };

    const int t0 = blockIdx.x;            // first tile of this CTA
    const int gstride = (int)gridDim.x;

    // prologue: fill 3 stages from tile t0 (kt = 0,1,2), prime step-0 operands
    {
        const int m0 = (t0 & 31) * BM, n0 = (t0 >> 5) * BN;
#pragma unroll
        for (int s = 0; s < STAGES - 1; ++s) {
            load_stage(s, m0, n0, s);
            CP_COMMIT();
        }
    }
    uint32_t a[2][4][4], b[2][4][4];
    CP_WAIT2();
    __syncthreads();
    ldsm_step(0, 0, a[0], b[0]);

    for (int p = 0, t = t0; t < NTILES; ++p, t += gstride) {
        const int cm0 = (t & 31) * BM, cn0 = (t >> 5) * BN;
        const bool last_tile = (t + gstride) >= NTILES;

        for (int it = 0; it < KITERS; ++it) {
            const int s = it & 3;
            const int sn = (it + 1) & 3;
            // load flat index fc+3 (may belong to next tile)
            {
                int nit = it + 3;
                int lt = t + (nit >> 6) * gstride;
                if (lt < NTILES) {
                    load_stage(nit & 63, (lt & 31) * BM, (lt >> 5) * BN, nit & 3);
                }
                CP_COMMIT();   // always commit to keep group counting uniform
            }
            // ks = 0
            ldsm_step(s, 1, a[1], b[1]);
            mma_step(a[0], b[0]);
            // ks = 1
            ldsm_step(s, 2, a[0], b[0]);
            mma_step(a[1], b[1]);
            // ks = 2: last read of stage s; wait+sync hidden behind pending HMMAs
            ldsm_step(s, 3, a[1], b[1]);
            mma_step(a[0], b[0]);
            CP_WAIT2();        // flat stage fc+1 complete (2 newest in flight)
            __syncthreads();   // visibility + slot-reuse fence
            // ks = 3: prefetch step 0 of next flat stage (possibly next tile)
            if (it + 1 < KITERS || !last_tile)
                ldsm_step(sn, 0, a[0], b[0]);
            mma_step(a[1], b[1]);
        }

        // epilogue for tile t: direct fp32 stores, then reset accumulators.
        // cp.async for upcoming stages continue in the background.
#pragma unroll
        for (int mi = 0; mi < 4; ++mi) {
            int row = cm0 + wm + mi * 16 + (lane >> 2);
#pragma unroll
            for (int ni = 0; ni < 8; ++ni) {
                int col = cn0 + wn + ni * 8 + (lane & 3) * 2;
                float2* p0 = reinterpret_cast<float2*>(out + (size_t)row * N_DIM + col);
                float2* p1 = reinterpret_cast<float2*>(out + (size_t)(row + 8) * N_DIM + col);
                *p0 = make_float2(acc[mi][ni][0], acc[mi][ni][1]);
                *p1 = make_float2(acc[mi][ni][2], acc[mi][ni][3]);
            }
        }
#pragma unroll
        for (int i = 0; i < 4; ++i)
#pragma unroll
            for (int j = 0; j < 8; ++j)
#pragma unroll
                for (int r = 0; r < 4; ++r) acc[i][j][r] = 0.f;
    }
}

// ---------------------------------------------------------------------------
// Launch
// ---------------------------------------------------------------------------
extern "C" void kernel_launch(void* const* d_in, const int* in_sizes, int n_in,
                              void* d_out, int out_size) {
    const int*   rows = (const int*)d_in[0];
    const int*   cols = (const int*)d_in[1];
    const float* vals = (const float*)d_in[2];
    const float* x    = (const float*)d_in[3];
    float* out = (float*)d_out;
    int nnz = in_sizes[0];

    static int nsm = 0;
    if (!nsm) {
        cudaDeviceProp prop;
        cudaGetDeviceProperties(&prop, 0);
        nsm = prop.multiProcessorCount;
        if (nsm <= 0 || nsm > NTILES) nsm = 148;
        cudaFuncSetAttribute(gemm_kernel, cudaFuncAttributeMaxDynamicSharedMemorySize,
                             SMEM_TOTAL);
    }

    prep_kernel<<<dim3(K_DIM / 64, 136), 256>>>(x);
    scatter_kernel<<<(nnz + 255) / 256, 256>>>(rows, cols, vals, nnz);
    gemm_kernel<<<nsm, THREADS, SMEM_TOTAL>>>(out);
}

// round 10
// speedup vs baseline: 1.1037x; 1.1037x over previous
#include <cuda_runtime.h>
#include <cuda_fp16.h>
#include <cstdint>

// ---------------------------------------------------------------------------
// Problem constants
// ---------------------------------------------------------------------------
#define M_DIM 4096      // out features
#define K_DIM 4096      // in features
#define N_DIM 8192      // cols of x / out
#define BM 128          // CTA tile M
#define BN 256          // CTA tile N
#define BK 64           // K per stage
#define ITERS (K_DIM / BK)   // 64
#define STAGES 4
#define THREADS 256     // 8 warps, 2(m) x 4(n), warp tile 64x64

// smem rows: 64 halves = 128B data + 16B pad = 144B (conflict-free ldmatrix)
#define ROW_B 144
#define A_STAGE_B (BM * ROW_B)            // 18432
#define B_STAGE_B (BN * ROW_B)            // 36864
#define STAGE_B (A_STAGE_B + B_STAGE_B)   // 55296
#define SMEM_TOTAL (STAGES * STAGE_B)     // 221184

// ---------------------------------------------------------------------------
// Device scratch. Packed k-major 64-wide panels:
//   elem(m, k) -> g_Wh[ ((k>>6)*M_DIM + m)*64 + (k&63) ]
//   elem(n, k) -> g_Xh[ ((k>>6)*N_DIM + n)*64 + (k&63) ]
// ---------------------------------------------------------------------------
__device__ unsigned short g_Wh[(size_t)M_DIM * K_DIM];   // 32 MB fp16
__device__ unsigned short g_Xh[(size_t)N_DIM * K_DIM];   // 64 MB fp16

// ---------------------------------------------------------------------------
// PTX helpers (sm_80-base ISA only)
// ---------------------------------------------------------------------------
__device__ __forceinline__ uint32_t smem_u32(const void* p) {
    uint32_t a;
    asm("{ .reg .u64 t; cvta.to.shared.u64 t, %1; cvt.u32.u64 %0, t; }" : "=r"(a) : "l"(p));
    return a;
}

__device__ __forceinline__ void cp16(uint32_t dst, const void* src) {
    asm volatile("cp.async.cg.shared.global [%0], [%1], 16;" :: "r"(dst), "l"(src));
}

#define CP_COMMIT() asm volatile("cp.async.commit_group;" ::: "memory")
#define CP_WAIT2()  asm volatile("cp.async.wait_group 2;" ::: "memory")

__device__ __forceinline__ void ldsm4(uint32_t r[4], uint32_t addr) {
    asm volatile("ldmatrix.sync.aligned.m8n8.x4.shared.b16 {%0,%1,%2,%3}, [%4];"
        : "=r"(r[0]), "=r"(r[1]), "=r"(r[2]), "=r"(r[3]) : "r"(addr));
}

__device__ __forceinline__ void mma16816(float d[4], const uint32_t a[4],
                                         uint32_t b0, uint32_t b1) {
    asm volatile(
        "mma.sync.aligned.m16n8k16.row.col.f32.f16.f16.f32 "
        "{%0,%1,%2,%3}, {%4,%5,%6,%7}, {%8,%9}, {%0,%1,%2,%3};"
        : "+f"(d[0]), "+f"(d[1]), "+f"(d[2]), "+f"(d[3])
        : "r"(a[0]), "r"(a[1]), "r"(a[2]), "r"(a[3]), "r"(b0), "r"(b1));
}

// ---------------------------------------------------------------------------
// Preprocessing: fused [packX | clearW] kernel (measured 37.7us), then scatter.
// grid = (64, 136): y < 128 -> packX 64x64 tile; y >= 128 -> clear W slice.
// ---------------------------------------------------------------------------
__global__ void prep_kernel(const float* __restrict__ x) {
    if (blockIdx.y < 128) {
        // ---- packX: transpose x[K,N] -> packed xT fp16 panels ----
        __shared__ float sh[64][65];
        const int k0 = blockIdx.x * 64;
        const int n0 = blockIdx.y * 64;
        const int t = threadIdx.x;    // 256 threads

        const float4* xv = reinterpret_cast<const float4*>(x + (size_t)k0 * N_DIM + n0);
#pragma unroll
        for (int i = 0; i < 4; ++i) {
            int idx = i * 256 + t;
            int kk = idx >> 4, c4 = idx & 15;
            float4 v = xv[(size_t)kk * (N_DIM / 4) + c4];
            sh[kk][c4 * 4 + 0] = v.x;
            sh[kk][c4 * 4 + 1] = v.y;
            sh[kk][c4 * 4 + 2] = v.z;
            sh[kk][c4 * 4 + 3] = v.w;
        }
        __syncthreads();
#pragma unroll
        for (int j = 0; j < 2; ++j) {  // 512 uint4 stores (64 n-rows x 8 octets)
            int idx = j * 256 + t;
            int nl = idx >> 3, oct = idx & 7;
            uint4 v;
            uint32_t* vp = &v.x;
#pragma unroll
            for (int q = 0; q < 4; ++q) {
                __half2 h2 = __floats2half2_rn(sh[oct * 8 + 2 * q][nl],
                                               sh[oct * 8 + 2 * q + 1][nl]);
                vp[q] = *reinterpret_cast<uint32_t*>(&h2);
            }
            size_t dst = ((size_t)blockIdx.x * N_DIM + n0 + nl) * 64 + oct * 8;
            *reinterpret_cast<uint4*>(&g_Xh[dst]) = v;
        }
    } else {
        // ---- clearW: 512 slices x 64KB ----
        int slice = blockIdx.x * 8 + (blockIdx.y - 128);   // 0..511
        uint4* p4 = reinterpret_cast<uint4*>(g_Wh) + (size_t)slice * 4096;
        uint4 z = make_uint4(0, 0, 0, 0);
#pragma unroll
        for (int i = 0; i < 16; ++i)
            p4[threadIdx.x + i * 256] = z;
    }
}

// Scatter COO directly into the packed fp16 panel layout with half atomics.
__global__ void scatter_kernel(const int* __restrict__ rows, const int* __restrict__ cols,
                               const float* __restrict__ vals, int nnz) {
    int i = blockIdx.x * blockDim.x + threadIdx.x;
    if (i < nnz) {
        int m = rows[i], k = cols[i];
        size_t idx = ((size_t)(k >> 6) * M_DIM + m) * 64 + (k & 63);
        atomicAdd(reinterpret_cast<__half*>(g_Wh) + idx, __float2half_rn(vals[i]));
    }
}

// ---------------------------------------------------------------------------
// Main GEMM (R5 champion, verbatim): out = W(fp16) * x(fp16), fp32 accum.
// CTA 128x256x64, 8 warps (2m x 4n), warp tile 64x64, 4-stage cp.async.
// CUTLASS-style rotation: wait+sync buried mid-k-loop behind pending MMAs;
// step-0 ldsm of the next stage prefetched at ks=3 so the tensor pipe never
// drains at stage boundaries. Measured: 531us, tensor 85.6%.
// ---------------------------------------------------------------------------
__global__ void __launch_bounds__(THREADS, 1) gemm_kernel(float* __restrict__ out) {
    extern __shared__ __align__(128) char smem[];
    const uint32_t sb = smem_u32(smem);
    const int tid = threadIdx.x;
    const int lane = tid & 31;
    const int wid = tid >> 5;
    const int wm = (wid & 1) * 64;    // warp m offset
    const int wn = (wid >> 1) * 64;   // warp n offset
    const int m0 = blockIdx.x * BM;
    const int n0 = blockIdx.y * BN;

    float acc[4][8][4];
#pragma unroll
    for (int i = 0; i < 4; ++i)
#pragma unroll
        for (int j = 0; j < 8; ++j)
#pragma unroll
            for (int r = 0; r < 4; ++r) acc[i][j][r] = 0.f;

    const uint32_t a_lane_off =
        (uint32_t)((wm + (lane & 15)) * ROW_B + (lane >> 4) * 16);
    const uint32_t b_lane_off =
        (uint32_t)((wn + (lane & 7) + ((lane >> 4) & 1) * 8) * ROW_B +
                   ((lane >> 3) & 1) * 16);

    auto load_stage = [&](int kt, int s) {
        const char* asrc = (const char*)g_Wh + ((size_t)kt * M_DIM + m0) * 128;
        const char* bsrc = (const char*)g_Xh + ((size_t)kt * N_DIM + n0) * 128;
        uint32_t As = sb + s * STAGE_B;
        uint32_t Bs = As + A_STAGE_B;
#pragma unroll
        for (int j = 0; j < 4; ++j) {   // A: 1024 x 16B chunks (8 per 128B row)
            int c = tid + j * THREADS;
            cp16(As + (uint32_t)((c >> 3) * ROW_B + (c & 7) * 16), asrc + (size_t)c * 16);
        }
#pragma unroll
        for (int j = 0; j < 8; ++j) {   // B: 2048 x 16B chunks
            int c = tid + j * THREADS;
            cp16(Bs + (uint32_t)((c >> 3) * ROW_B + (c & 7) * 16), bsrc + (size_t)c * 16);
        }
    };

    auto ldsm_step = [&](int s, int ks, uint32_t a[4][4], uint32_t b[4][4]) {
        const uint32_t As = sb + s * STAGE_B + a_lane_off + ks * 32;
        const uint32_t Bs = sb + s * STAGE_B + A_STAGE_B + b_lane_off + ks * 32;
#pragma unroll
        for (int mi = 0; mi < 4; ++mi) ldsm4(a[mi], As + mi * (16 * ROW_B));
#pragma unroll
        for (int nj = 0; nj < 4; ++nj) ldsm4(b[nj], Bs + nj * (16 * ROW_B));
    };

    auto mma_step = [&](uint32_t a[4][4], uint32_t b[4][4]) {
#pragma unroll
        for (int mi = 0; mi < 4; ++mi)
#pragma unroll
            for (int nj = 0; nj < 4; ++nj) {
                mma16816(acc[mi][2 * nj], a[mi], b[nj][0], b[nj][1]);
                mma16816(acc[mi][2 * nj + 1], a[mi], b[nj][2], b[nj][3]);
            }
    };

    // prologue: fill 3 of 4 stages, then prime step-0 operands of stage 0
#pragma unroll
    for (int s = 0; s < STAGES - 1; ++s) {
        load_stage(s, s);
        CP_COMMIT();
    }
    uint32_t a[2][4][4], b[2][4][4];
    CP_WAIT2();           // stage 0 complete
    __syncthreads();      // cross-thread visibility
    ldsm_step(0, 0, a[0], b[0]);

    for (int it = 0; it < ITERS; ++it) {
        const int s = it & (STAGES - 1);
        // Issue next gmem loads while tensor pipe drains previous MMAs.
        // Slot (it+3)&3 was last READ before the sync at iter it-1's ks==2.
        if (it + 3 < ITERS) load_stage(it + 3, (it + 3) & (STAGES - 1));
        CP_COMMIT();       // always commit to keep group counting uniform

        // ks = 0
        ldsm_step(s, 1, a[1], b[1]);
        mma_step(a[0], b[0]);
        // ks = 1
        ldsm_step(s, 2, a[0], b[0]);
        mma_step(a[1], b[1]);
        // ks = 2: last read of stage s issued, then wait+sync hidden behind
        //         the 32 pending HMMAs of this mma_step.
        ldsm_step(s, 3, a[1], b[1]);
        mma_step(a[0], b[0]);
        CP_WAIT2();        // guarantees stage it+1 complete (2 newest in flight)
        __syncthreads();   // visibility for stage it+1 + slot reuse protection
        // ks = 3: prefetch step 0 of next stage, then final mma of stage s.
        if (it + 1 < ITERS) ldsm_step((it + 1) & (STAGES - 1), 0, a[0], b[0]);
        mma_step(a[1], b[1]);
    }

    // epilogue: direct fp32 stores
#pragma unroll
    for (int mi = 0; mi < 4; ++mi) {
        int row = m0 + wm + mi * 16 + (lane >> 2);
#pragma unroll
        for (int ni = 0; ni < 8; ++ni) {
            int col = n0 + wn + ni * 8 + (lane & 3) * 2;
            float2* p0 = reinterpret_cast<float2*>(out + (size_t)row * N_DIM + col);
            float2* p1 = reinterpret_cast<float2*>(out + (size_t)(row + 8) * N_DIM + col);
            *p0 = make_float2(acc[mi][ni][0], acc[mi][ni][1]);
            *p1 = make_float2(acc[mi][ni][2], acc[mi][ni][3]);
        }
    }
}

// ---------------------------------------------------------------------------
// Launch
// ---------------------------------------------------------------------------
extern "C" void kernel_launch(void* const* d_in, const int* in_sizes, int n_in,
                              void* d_out, int out_size) {
    const int*   rows = (const int*)d_in[0];
    const int*   cols = (const int*)d_in[1];
    const float* vals = (const float*)d_in[2];
    const float* x    = (const float*)d_in[3];
    float* out = (float*)d_out;
    int nnz = in_sizes[0];

    static int smem_set = 0;
    if (!smem_set) {
        cudaFuncSetAttribute(gemm_kernel, cudaFuncAttributeMaxDynamicSharedMemorySize,
                             SMEM_TOTAL);
        smem_set = 1;
    }

    prep_kernel<<<dim3(K_DIM / 64, 136), 256>>>(x);
    scatter_kernel<<<(nnz + 255) / 256, 256>>>(rows, cols, vals, nnz);
    gemm_kernel<<<dim3(M_DIM / BM, N_DIM / BN), THREADS, SMEM_TOTAL>>>(out);
}